// round 1
// baseline (speedup 1.0000x reference)
#include <cuda_runtime.h>

#define Bn 16
#define Qn 64
#define Kn 1024
#define Dn 256
#define Hn 128

// Scratch (device globals: no allocation allowed in kernel_launch)
__device__ float g_qp[Bn*Qn*Hn];    // projected queries  [B,Q,H]
__device__ float g_kp[Bn*Kn*Hn];    // projected keys     [B,K,H]
__device__ float g_attn[Bn*Qn*Kn];  // scores -> attn in place [B,Q,K]

// ---------- packed f32x2 helpers (Blackwell) ----------
__device__ __forceinline__ unsigned long long pack2(float x, float y){
    unsigned long long r; asm("mov.b64 %0, {%1,%2};" : "=l"(r) : "f"(x), "f"(y)); return r;
}
__device__ __forceinline__ unsigned long long fma2(unsigned long long a, unsigned long long b, unsigned long long c){
    unsigned long long d; asm("fma.rn.f32x2 %0, %1, %2, %3;" : "=l"(d) : "l"(a), "l"(b), "l"(c)); return d;
}
__device__ __forceinline__ void unpack2(unsigned long long v, float& lo, float& hi){
    asm("mov.b64 {%0,%1}, %2;" : "=f"(lo), "=f"(hi) : "l"(v));
}
__device__ __forceinline__ float tanh_fast(float x){
    float y; asm("tanh.approx.f32 %0, %1;" : "=f"(y) : "f"(x)); return y;
}

// ---------------- projection: out[M,H] = X[M,D] @ W[D,H] ----------------
#define PR 32    // rows per block
#define PT 128   // threads (= Hn)
#define XS 36    // padded smem row stride (floats): 16B-aligned pairs, low conflicts

template<int WHICH>
__global__ __launch_bounds__(PT) void proj_kernel(const float* __restrict__ X,
                                                  const float* __restrict__ W){
    __shared__ float xs[Dn*XS];   // X tile transposed: xs[d][r]
    float* out = WHICH ? g_kp : g_qp;
    const int row0 = blockIdx.x * PR;
    const int t = threadIdx.x;

    for (int i = t; i < PR*Dn; i += PT){
        int r = i >> 8;          // /256
        int d = i & (Dn-1);
        xs[d*XS + r] = X[(row0 + r)*Dn + d];
    }
    __syncthreads();

    unsigned long long acc[PR/2];
#pragma unroll
    for (int i = 0; i < PR/2; i++) acc[i] = 0ull;

#pragma unroll 2
    for (int d = 0; d < Dn; d++){
        float w = W[d*Hn + t];                       // coalesced, L1/L2-hot
        unsigned long long w2 = pack2(w, w);
        const ulonglong2* xp = reinterpret_cast<const ulonglong2*>(&xs[d*XS]);
#pragma unroll
        for (int m = 0; m < PR/4; m++){
            ulonglong2 xv = xp[m];                   // 1 LDS.128 = 2 f32x2 row pairs
            acc[2*m]   = fma2(w2, xv.x, acc[2*m]);
            acc[2*m+1] = fma2(w2, xv.y, acc[2*m+1]);
        }
    }
#pragma unroll
    for (int i = 0; i < PR/2; i++){
        float lo, hi; unpack2(acc[i], lo, hi);
        out[(row0 + 2*i    )*Hn + t] = lo;
        out[(row0 + 2*i + 1)*Hn + t] = hi;
    }
}

// --------- scores: s[b,q,k] = sum_h w_v[h] * tanh(qp[b,q,h] + kp[b,k,h]) ---------
// mask-aware: skips k >= valid_len entirely (softmax/out never read those).
#define SKT 32   // k per block
#define SQT 16   // q per block
#define ST  256  // threads: 32 k-lanes x 8 q-phases

__global__ __launch_bounds__(ST) void score_kernel(const float* __restrict__ wv,
                                                   const int* __restrict__ vlen){
    const int b  = blockIdx.z;
    const int v  = vlen[b];
    const int k0 = blockIdx.x * SKT;
    if (k0 >= v) return;                       // fully masked tile: nothing to do
    const int kmax = min(SKT, v - k0);

    __shared__ float ks[SKT*Hn];               // swizzled kp tile (512B rows, c ^= j&7)
    __shared__ float ws[Hn];
    const int t = threadIdx.x;
    if (t < Hn) ws[t] = wv[t];

    const float* kpb = g_kp + (size_t)(b*Kn + k0)*Hn;
    for (int i = t; i < SKT*Hn; i += ST){
        int j = i >> 7, h = i & 127;
        int sidx = j*Hn + ((((h>>2) ^ (j & 7))) << 2) + (h & 3);
        ks[sidx] = kpb[i];
    }
    __syncthreads();

    const int j  = t & 31;        // k lane
    const int qh = t >> 5;        // q phase 0..7
    const int jx = j & 7;         // swizzle key
    const int q0 = blockIdx.y * SQT;
    const float* qpb = g_qp + (size_t)b*Qn*Hn;
    float* sc = g_attn + (size_t)b*Qn*Kn;

#pragma unroll
    for (int qi = 0; qi < SQT/8; qi++){
        const int q = q0 + qi*8 + qh;
        const float4* qrow = reinterpret_cast<const float4*>(qpb + q*Hn);
        float acc = 0.f;
#pragma unroll 8
        for (int c = 0; c < Hn/4; c++){
            float4 kv = *reinterpret_cast<const float4*>(&ks[j*Hn + ((c ^ jx) << 2)]);
            float4 qv = qrow[c];                                  // warp-uniform LDG
            float4 w4 = *reinterpret_cast<const float4*>(&ws[c << 2]);
            acc += w4.x * tanh_fast(qv.x + kv.x);
            acc += w4.y * tanh_fast(qv.y + kv.y);
            acc += w4.z * tanh_fast(qv.z + kv.z);
            acc += w4.w * tanh_fast(qv.w + kv.w);
        }
        if (j < kmax) sc[q*Kn + k0 + j] = acc;
    }
}

// ---------------- masked softmax over k (in place on g_attn) ----------------
#define SMT 128
__global__ __launch_bounds__(SMT) void softmax_kernel(const int* __restrict__ vlen){
    const int bq = blockIdx.x;
    const int b = bq >> 6;                 // Qn = 64
    const int v = vlen[b];
    float* row = g_attn + (size_t)bq*Kn;
    const int t = threadIdx.x;

    float vals[Kn/SMT];
    float m = -1e30f;
#pragma unroll
    for (int i = 0; i < Kn/SMT; i++){
        int k = t + i*SMT;
        vals[i] = (k < v) ? row[k] : -1e30f;
        m = fmaxf(m, vals[i]);
    }
    __shared__ float redm[4];
#pragma unroll
    for (int o = 16; o > 0; o >>= 1) m = fmaxf(m, __shfl_xor_sync(0xffffffffu, m, o));
    if ((t & 31) == 0) redm[t >> 5] = m;
    __syncthreads();
    m = fmaxf(fmaxf(redm[0], redm[1]), fmaxf(redm[2], redm[3]));

    float s = 0.f;
#pragma unroll
    for (int i = 0; i < Kn/SMT; i++){ vals[i] = __expf(vals[i] - m); s += vals[i]; }
#pragma unroll
    for (int o = 16; o > 0; o >>= 1) s += __shfl_xor_sync(0xffffffffu, s, o);
    __shared__ float reds[4];
    if ((t & 31) == 0) reds[t >> 5] = s;
    __syncthreads();
    s = reds[0] + reds[1] + reds[2] + reds[3];
    const float inv = __fdividef(1.f, s);

#pragma unroll
    for (int i = 0; i < Kn/SMT; i++){
        int k = t + i*SMT;
        if (k < v) row[k] = vals[i]*inv;
    }
}

// ---------------- output: out[b,q,d] = sum_{k<v} attn[b,q,k] * V[b,k,d] ----------------
#define OQT 8    // q rows per block
#define OTK 64   // k tile
#define OT  128  // threads: one float2 of d per thread

__global__ __launch_bounds__(OT) void out_kernel(const float* __restrict__ V,
                                                 const int* __restrict__ vlen,
                                                 float* __restrict__ out){
    const int b  = blockIdx.y;
    const int q0 = blockIdx.x * OQT;
    const int v  = vlen[b];
    __shared__ float as[OTK*OQT];     // attn tile transposed: as[k][r], 16B rows
    const int t = threadIdx.x;

    float2 acc[OQT];
#pragma unroll
    for (int r = 0; r < OQT; r++) acc[r] = make_float2(0.f, 0.f);

    const float*  attb = g_attn + (size_t)(b*Qn + q0)*Kn;
    const float2* V2   = reinterpret_cast<const float2*>(V + (size_t)b*Kn*Dn);

    for (int kt = 0; kt < v; kt += OTK){
        const int kn = min(OTK, v - kt);
        __syncthreads();
        for (int i = t; i < OQT*OTK; i += OT){
            int r = i >> 6, k = i & 63;
            as[k*OQT + r] = (k < kn) ? attb[r*Kn + kt + k] : 0.f;
        }
        __syncthreads();
#pragma unroll 4
        for (int k = 0; k < kn; k++){
            float2 vv = V2[(size_t)(kt + k)*(Dn/2) + t];
            float4 a0 = *reinterpret_cast<const float4*>(&as[k*OQT]);
            float4 a1 = *reinterpret_cast<const float4*>(&as[k*OQT + 4]);
            acc[0].x += a0.x*vv.x; acc[0].y += a0.x*vv.y;
            acc[1].x += a0.y*vv.x; acc[1].y += a0.y*vv.y;
            acc[2].x += a0.z*vv.x; acc[2].y += a0.z*vv.y;
            acc[3].x += a0.w*vv.x; acc[3].y += a0.w*vv.y;
            acc[4].x += a1.x*vv.x; acc[4].y += a1.x*vv.y;
            acc[5].x += a1.y*vv.x; acc[5].y += a1.y*vv.y;
            acc[6].x += a1.z*vv.x; acc[6].y += a1.z*vv.y;
            acc[7].x += a1.w*vv.x; acc[7].y += a1.w*vv.y;
        }
    }
    float2* ob = reinterpret_cast<float2*>(out + (size_t)(b*Qn + q0)*Dn);
#pragma unroll
    for (int r = 0; r < OQT; r++) ob[r*(Dn/2) + t] = acc[r];
}

// ---------------- launch ----------------
extern "C" void kernel_launch(void* const* d_in, const int* in_sizes, int n_in,
                              void* d_out, int out_size){
    const float* queries = (const float*)d_in[0];
    const float* keys    = (const float*)d_in[1];
    const float* values  = (const float*)d_in[2];
    const int*   vlen    = (const int*)  d_in[3];
    const float* W_q     = (const float*)d_in[4];
    const float* W_k     = (const float*)d_in[5];
    const float* w_v     = (const float*)d_in[6];
    float* out = (float*)d_out;

    proj_kernel<0><<<(Bn*Qn)/PR, PT>>>(queries, W_q);   // 32 blocks
    proj_kernel<1><<<(Bn*Kn)/PR, PT>>>(keys,    W_k);   // 512 blocks
    score_kernel<<<dim3(Kn/SKT, Qn/SQT, Bn), ST>>>(w_v, vlen);  // 2048 blocks
    softmax_kernel<<<Bn*Qn, SMT>>>(vlen);               // 1024 blocks
    out_kernel<<<dim3(Qn/OQT, Bn), OT>>>(values, vlen, out);    // 128 blocks
}

// round 2
// speedup vs baseline: 2.0482x; 2.0482x over previous
#include <cuda_runtime.h>

#define Bn 16
#define Qn 64
#define Kn 1024
#define Dn 256
#define Hn 128

// Scratch (device globals: no allocation allowed)
__device__ float g_qp[Bn*Qn*Hn];       // projected queries  [B,Q,H]
__device__ float g_kp[Bn*Kn*Hn];       // projected keys     [B,K,H]
__device__ float g_attn[Bn*Qn*Kn];     // scores -> exp(s-m) in place [B,Q,K]
__device__ float g_inv[Bn*Qn];         // 1/sum_exp per row
#define KS 8
#define OKS (Kn/KS)                    // 128 k per split
__device__ float g_part[KS*Bn*Qn*Dn];  // output partials [KS][B,Q,D] (8MB)

// ---------- packed f32x2 helpers (Blackwell) ----------
__device__ __forceinline__ unsigned long long pack2(float x, float y){
    unsigned long long r; asm("mov.b64 %0, {%1,%2};" : "=l"(r) : "f"(x), "f"(y)); return r;
}
__device__ __forceinline__ unsigned long long fma2(unsigned long long a, unsigned long long b, unsigned long long c){
    unsigned long long d; asm("fma.rn.f32x2 %0, %1, %2, %3;" : "=l"(d) : "l"(a), "l"(b), "l"(c)); return d;
}
__device__ __forceinline__ void unpack2(unsigned long long v, float& lo, float& hi){
    asm("mov.b64 {%0,%1}, %2;" : "=f"(lo), "=f"(hi) : "l"(v));
}
__device__ __forceinline__ float tanh_fast(float x){
    float y; asm("tanh.approx.f32 %0, %1;" : "=f"(y) : "f"(x)); return y;
}

// ---------------- projection (q and k fused into one launch) ----------------
#define PR 32    // rows per block
#define PT 128   // threads (= Hn)
#define XS 36    // padded smem row stride (floats); 36*4=144B keeps 16B alignment
#define QBLOCKS ((Bn*Qn)/PR)   // 32
#define KBLOCKS ((Bn*Kn)/PR)   // 512

__global__ __launch_bounds__(PT) void proj_kernel(const float* __restrict__ Xq,
                                                  const float* __restrict__ Wq,
                                                  const float* __restrict__ Xk,
                                                  const float* __restrict__ Wk){
    __shared__ float xs[Dn*XS];   // X tile transposed: xs[d][r]
    const float* X; const float* W; float* out; int row0;
    if (blockIdx.x < QBLOCKS){ X = Xq; W = Wq; out = g_qp; row0 = blockIdx.x * PR; }
    else                     { X = Xk; W = Wk; out = g_kp; row0 = (blockIdx.x - QBLOCKS) * PR; }
    const int t = threadIdx.x;

    for (int i = t; i < PR*Dn; i += PT){
        int r = i >> 8;          // /256
        int d = i & (Dn-1);
        xs[d*XS + r] = X[(row0 + r)*Dn + d];
    }
    __syncthreads();

    unsigned long long acc[PR/2];
#pragma unroll
    for (int i = 0; i < PR/2; i++) acc[i] = 0ull;

#pragma unroll 2
    for (int d = 0; d < Dn; d++){
        float w = W[d*Hn + t];                       // coalesced, L1-resident
        unsigned long long w2 = pack2(w, w);
        const ulonglong2* xp = reinterpret_cast<const ulonglong2*>(&xs[d*XS]);
#pragma unroll
        for (int m = 0; m < PR/4; m++){
            ulonglong2 xv = xp[m];                   // warp-uniform LDS.128 broadcast
            acc[2*m]   = fma2(w2, xv.x, acc[2*m]);
            acc[2*m+1] = fma2(w2, xv.y, acc[2*m+1]);
        }
    }
#pragma unroll
    for (int i = 0; i < PR/2; i++){
        float lo, hi; unpack2(acc[i], lo, hi);
        out[(row0 + 2*i    )*Hn + t] = lo;
        out[(row0 + 2*i + 1)*Hn + t] = hi;
    }
}

// --------- scores: s[b,q,k] = sum_h w_v[h] * tanh(qp[b,q,h] + kp[b,k,h]) ---------
#define SKT 32
#define SQT 16
#define ST  256

__global__ __launch_bounds__(ST) void score_kernel(const float* __restrict__ wv,
                                                   const int* __restrict__ vlen){
    const int b  = blockIdx.z;
    const int v  = vlen[b];
    const int k0 = blockIdx.x * SKT;
    if (k0 >= v) return;
    const int kmax = min(SKT, v - k0);

    __shared__ float ks[SKT*Hn];     // swizzled kp tile
    __shared__ float qs[SQT*Hn];     // q tile (plain)
    __shared__ float ws[Hn];
    const int t = threadIdx.x;
    if (t < Hn) ws[t] = wv[t];

    const float* kpb = g_kp + (size_t)(b*Kn + k0)*Hn;
    for (int i = t; i < SKT*Hn; i += ST){
        int j = i >> 7, h = i & 127;
        int sidx = j*Hn + ((((h>>2) ^ (j & 7))) << 2) + (h & 3);
        ks[sidx] = kpb[i];
    }
    const int q0 = blockIdx.y * SQT;
    const float* qpb = g_qp + (size_t)(b*Qn + q0)*Hn;
    for (int i = t; i < SQT*Hn; i += ST) qs[i] = qpb[i];
    __syncthreads();

    const int j  = t & 31;        // k lane
    const int qh = t >> 5;        // q phase 0..7 (uniform within warp)
    const int jx = j & 7;
    float* sc = g_attn + (size_t)(b*Qn + q0)*Kn;

#pragma unroll
    for (int qi = 0; qi < SQT/8; qi++){
        const int q = qi*8 + qh;
        float acc0 = 0.f, acc1 = 0.f;
#pragma unroll 8
        for (int c = 0; c < Hn/4; c++){
            float4 kv = *reinterpret_cast<const float4*>(&ks[j*Hn + ((c ^ jx) << 2)]);
            float4 qv = *reinterpret_cast<const float4*>(&qs[q*Hn + (c << 2)]); // broadcast
            float4 w4 = *reinterpret_cast<const float4*>(&ws[c << 2]);
            acc0 += w4.x * tanh_fast(qv.x + kv.x);
            acc1 += w4.y * tanh_fast(qv.y + kv.y);
            acc0 += w4.z * tanh_fast(qv.z + kv.z);
            acc1 += w4.w * tanh_fast(qv.w + kv.w);
        }
        if (j < kmax) sc[q*Kn + k0 + j] = acc0 + acc1;
    }
}

// ------------- softexp: row -> exp(row - max); store 1/sum to g_inv -------------
#define SMT 128
__global__ __launch_bounds__(SMT) void softexp_kernel(const int* __restrict__ vlen){
    const int bq = blockIdx.x;
    const int b = bq >> 6;
    const int v = vlen[b];
    float* row = g_attn + (size_t)bq*Kn;
    const int t = threadIdx.x;

    float vals[Kn/SMT];
    float m = -1e30f;
#pragma unroll
    for (int i = 0; i < Kn/SMT; i++){
        int k = t + i*SMT;
        vals[i] = (k < v) ? row[k] : -1e30f;
        m = fmaxf(m, vals[i]);
    }
    __shared__ float redm[4];
#pragma unroll
    for (int o = 16; o > 0; o >>= 1) m = fmaxf(m, __shfl_xor_sync(0xffffffffu, m, o));
    if ((t & 31) == 0) redm[t >> 5] = m;
    __syncthreads();
    m = fmaxf(fmaxf(redm[0], redm[1]), fmaxf(redm[2], redm[3]));

    float s = 0.f;
#pragma unroll
    for (int i = 0; i < Kn/SMT; i++){ vals[i] = __expf(vals[i] - m); s += vals[i]; }
#pragma unroll
    for (int o = 16; o > 0; o >>= 1) s += __shfl_xor_sync(0xffffffffu, s, o);
    __shared__ float reds[4];
    if ((t & 31) == 0) reds[t >> 5] = s;
    __syncthreads();
    s = reds[0] + reds[1] + reds[2] + reds[3];

#pragma unroll
    for (int i = 0; i < Kn/SMT; i++){
        int k = t + i*SMT;
        if (k < v) row[k] = vals[i];         // store raw exp; divide folded into reduce
    }
    if (t == 0) g_inv[bq] = __fdividef(1.f, s);
}

// --------- out partials: part[kz][b,q,d] = sum_{k in slice, k<v} e[b,q,k]*V[b,k,d] ---------
#define OQT 8
#define OT  128   // d2 lanes: thread owns d = {2t, 2t+1}

__global__ __launch_bounds__(OT) void outpart_kernel(const float* __restrict__ V,
                                                     const int* __restrict__ vlen){
    const int qt = blockIdx.x;    // 0..7
    const int kz = blockIdx.y;    // 0..KS-1
    const int b  = blockIdx.z;
    const int v  = vlen[b];
    const int k0 = kz * OKS;
    const int q0 = qt * OQT;
    const int t  = threadIdx.x;
    float* part = g_part + ((size_t)kz*Bn*Qn + b*Qn + q0)*Dn;

    if (k0 >= v){
        float2 z = make_float2(0.f, 0.f);
#pragma unroll
        for (int r = 0; r < OQT; r++)
            reinterpret_cast<float2*>(part + r*Dn)[t] = z;
        return;
    }
    const int kmax = min(OKS, v - k0);

    __shared__ float as[OKS][OQT];   // e values, q-contiguous rows (32B, 16B-aligned)
    const float* attb = g_attn + (size_t)(b*Qn + q0)*Kn + k0;
    for (int i = t; i < OQT*OKS; i += OT){
        int q = i >> 7, k = i & (OKS-1);
        if (k < kmax) as[k][q] = attb[q*Kn + k];
    }
    __syncthreads();

    const float2* V2 = reinterpret_cast<const float2*>(V + ((size_t)b*Kn + k0)*Dn);
    unsigned long long accA[4] = {0,0,0,0};   // (q2r,q2r+1) x d0
    unsigned long long accB[4] = {0,0,0,0};   // (q2r,q2r+1) x d1

#pragma unroll 4
    for (int k = 0; k < kmax; k++){
        float2 vv = V2[(size_t)k*(Dn/2) + t];
        unsigned long long v0 = pack2(vv.x, vv.x);
        unsigned long long v1 = pack2(vv.y, vv.y);
        const ulonglong2* ap = reinterpret_cast<const ulonglong2*>(as[k]); // broadcast
        ulonglong2 a01 = ap[0];
        ulonglong2 a23 = ap[1];
        accA[0] = fma2(a01.x, v0, accA[0]);  accB[0] = fma2(a01.x, v1, accB[0]);
        accA[1] = fma2(a01.y, v0, accA[1]);  accB[1] = fma2(a01.y, v1, accB[1]);
        accA[2] = fma2(a23.x, v0, accA[2]);  accB[2] = fma2(a23.x, v1, accB[2]);
        accA[3] = fma2(a23.y, v0, accA[3]);  accB[3] = fma2(a23.y, v1, accB[3]);
    }

#pragma unroll
    for (int r = 0; r < 4; r++){
        float fa, fb, ga, gb;
        unpack2(accA[r], fa, fb);   // fa: q=2r,d0   fb: q=2r+1,d0
        unpack2(accB[r], ga, gb);   // ga: q=2r,d1   gb: q=2r+1,d1
        reinterpret_cast<float2*>(part + (2*r  )*Dn)[t] = make_float2(fa, ga);
        reinterpret_cast<float2*>(part + (2*r+1)*Dn)[t] = make_float2(fb, gb);
    }
}

// ---------------- reduce: out = inv_sum * sum_s part[s] ----------------
#define RT 128
#define NOUT4 ((Bn*Qn*Dn)/4)   // 65536 float4

__global__ __launch_bounds__(RT) void reduce_kernel(float* __restrict__ out){
    const int i4 = blockIdx.x * RT + threadIdx.x;
    const float4* p = reinterpret_cast<const float4*>(g_part);
    float4 s = p[i4];
#pragma unroll
    for (int z = 1; z < KS; z++){
        float4 x = p[(size_t)z*NOUT4 + i4];
        s.x += x.x; s.y += x.y; s.z += x.z; s.w += x.w;
    }
    const float inv = g_inv[i4 >> 6];    // 64 float4 per (b,q) row (Dn/4)
    s.x *= inv; s.y *= inv; s.z *= inv; s.w *= inv;
    reinterpret_cast<float4*>(out)[i4] = s;
}

// ---------------- launch ----------------
extern "C" void kernel_launch(void* const* d_in, const int* in_sizes, int n_in,
                              void* d_out, int out_size){
    const float* queries = (const float*)d_in[0];
    const float* keys    = (const float*)d_in[1];
    const float* values  = (const float*)d_in[2];
    const int*   vlen    = (const int*)  d_in[3];
    const float* W_q     = (const float*)d_in[4];
    const float* W_k     = (const float*)d_in[5];
    const float* w_v     = (const float*)d_in[6];
    float* out = (float*)d_out;

    proj_kernel<<<QBLOCKS + KBLOCKS, PT>>>(queries, W_q, keys, W_k);        // 544 blocks
    score_kernel<<<dim3(Kn/SKT, Qn/SQT, Bn), ST>>>(w_v, vlen);              // 2048 blocks
    softexp_kernel<<<Bn*Qn, SMT>>>(vlen);                                   // 1024 blocks
    outpart_kernel<<<dim3(Qn/OQT, KS, Bn), OT>>>(values, vlen);             // 1024 blocks
    reduce_kernel<<<NOUT4/RT, RT>>>(out);                                   // 512 blocks
}